// round 2
// baseline (speedup 1.0000x reference)
#include <cuda_runtime.h>
#include <math.h>

#define N_NODES 100000
#define N_EDGES 1600000
#define FULL 0xffffffffu

// ---- scratch (static device globals; no allocation allowed) ----
__device__ int   g_count[N_NODES];        // histogram, then scatter cursor
__device__ int   g_rowptr[N_NODES + 1];   // CSR row pointers (by dst)
__device__ float g_dinv[N_NODES];         // deg^-1/2 (deg includes self loop)
__device__ int   g_col[N_EDGES];          // CSR src indices
__device__ float g_nw[N_EDGES];           // per-edge norm = dinv[src]*dinv[dst]
__device__ __align__(16) float g_x1[N_NODES * 64];  // layer-1 output
__device__ __align__(16) float g_p[N_NODES * 10];   // x2 @ W3 (pre-agg logits)

// ---------------- CSR build ----------------
__global__ void k_zero() {
    int i = blockIdx.x * blockDim.x + threadIdx.x;
    if (i < N_NODES) g_count[i] = 0;
}

__global__ void k_hist(const int* __restrict__ ei) {
    int e = blockIdx.x * blockDim.x + threadIdx.x;
    if (e < N_EDGES) {
        int d = ei[N_EDGES + e];
        atomicAdd(&g_count[d], 1);
    }
}

// single-block exclusive scan over 100k counts; also dinv and count reset
__global__ void k_scan() {
    __shared__ int ssum[1024];
    const int tid = threadIdx.x;
    const int CH = (N_NODES + 1023) / 1024;  // 98
    int beg = tid * CH;
    int end = beg + CH; if (end > N_NODES) end = N_NODES;
    if (beg > N_NODES) beg = N_NODES;
    int s = 0;
    for (int i = beg; i < end; i++) s += g_count[i];
    ssum[tid] = s;
    __syncthreads();
    // inclusive Hillis-Steele scan of the 1024 partials
    for (int off = 1; off < 1024; off <<= 1) {
        int t = 0;
        if (tid >= off) t = ssum[tid - off];
        __syncthreads();
        ssum[tid] += t;
        __syncthreads();
    }
    int run = ssum[tid] - s;  // exclusive prefix for this chunk
    for (int i = beg; i < end; i++) {
        g_rowptr[i] = run;
        int c = g_count[i];
        run += c;
        g_dinv[i] = rsqrtf((float)c + 1.0f);  // + self loop
        g_count[i] = 0;                       // reset as scatter cursor
    }
    if (beg < N_NODES && end == N_NODES) g_rowptr[N_NODES] = run;
}

__global__ void k_scatter(const int* __restrict__ ei) {
    int e = blockIdx.x * blockDim.x + threadIdx.x;
    if (e < N_EDGES) {
        int s = ei[e];
        int d = ei[N_EDGES + e];
        int pos = g_rowptr[d] + atomicAdd(&g_count[d], 1);
        g_col[pos] = s;
        g_nw[pos] = g_dinv[s] * g_dinv[d];
    }
}

// ---------------- layer 1: agg(x)[13] -> @W1 +b1 -> relu -> x1[64] ----------------
__global__ void k_layer1(const float* __restrict__ x,
                         const float* __restrict__ W1,
                         const float* __restrict__ b1) {
    __shared__ float W1s[13 * 64];
    __shared__ float b1s[64];
    for (int i = threadIdx.x; i < 13 * 64; i += blockDim.x) W1s[i] = W1[i];
    for (int i = threadIdx.x; i < 64; i += blockDim.x) b1s[i] = b1[i];
    __syncthreads();

    int v = (blockIdx.x * blockDim.x + threadIdx.x) >> 5;
    int lane = threadIdx.x & 31;
    if (v >= N_NODES) return;

    float di = g_dinv[v];
    float a = (lane < 13) ? di * di * x[v * 13 + lane] : 0.0f;
    int beg = g_rowptr[v], end = g_rowptr[v + 1];
    for (int e0 = beg; e0 < end; e0 += 32) {
        int idx = e0 + lane;
        int c = 0; float w = 0.0f;
        if (idx < end) { c = g_col[idx]; w = g_nw[idx]; }
        int m = end - e0; if (m > 32) m = 32;
        for (int t = 0; t < m; t++) {
            int cc = __shfl_sync(FULL, c, t);
            float ww = __shfl_sync(FULL, w, t);
            if (lane < 13) a += ww * x[cc * 13 + lane];
        }
    }
    // GEMM 13 -> 64 (2 outputs per lane)
    float ox = b1s[2 * lane], oy = b1s[2 * lane + 1];
    for (int k = 0; k < 13; k++) {
        float av = __shfl_sync(FULL, a, k);
        ox += av * W1s[k * 64 + 2 * lane];
        oy += av * W1s[k * 64 + 2 * lane + 1];
    }
    float2 o = make_float2(fmaxf(ox, 0.0f), fmaxf(oy, 0.0f));
    ((float2*)(g_x1 + v * 64))[lane] = o;
}

// ---------------- layer 2: agg(x1)[64] -> @W2 +b2 relu + x1 -> @W3 -> p[10] ----------------
__global__ void k_layer2(const float* __restrict__ W2,
                         const float* __restrict__ b2,
                         const float* __restrict__ W3) {
    __shared__ float W2s[64 * 64];
    __shared__ float b2s[64];
    __shared__ float W3s[64 * 10];
    for (int i = threadIdx.x; i < 64 * 64; i += blockDim.x) W2s[i] = W2[i];
    for (int i = threadIdx.x; i < 64; i += blockDim.x) b2s[i] = b2[i];
    for (int i = threadIdx.x; i < 64 * 10; i += blockDim.x) W3s[i] = W3[i];
    __syncthreads();

    int v = (blockIdx.x * blockDim.x + threadIdx.x) >> 5;
    int lane = threadIdx.x & 31;
    if (v >= N_NODES) return;

    float di = g_dinv[v];
    float d2 = di * di;
    const float2 hv0 = ((const float2*)(g_x1 + v * 64))[lane];  // x1[v] slice
    float ax = d2 * hv0.x, ay = d2 * hv0.y;

    int beg = g_rowptr[v], end = g_rowptr[v + 1];
    for (int e0 = beg; e0 < end; e0 += 32) {
        int idx = e0 + lane;
        int c = 0; float w = 0.0f;
        if (idx < end) { c = g_col[idx]; w = g_nw[idx]; }
        int m = end - e0; if (m > 32) m = 32;
        for (int t = 0; t < m; t++) {
            int cc = __shfl_sync(FULL, c, t);
            float ww = __shfl_sync(FULL, w, t);
            float2 hv = ((const float2*)(g_x1 + cc * 64))[lane];
            ax += ww * hv.x;
            ay += ww * hv.y;
        }
    }
    // GEMM 64 -> 64
    float ox = b2s[2 * lane], oy = b2s[2 * lane + 1];
    for (int k2 = 0; k2 < 32; k2++) {
        float bx = __shfl_sync(FULL, ax, k2);
        float by = __shfl_sync(FULL, ay, k2);
        int k = 2 * k2;
        ox += bx * W2s[k * 64 + 2 * lane];
        oy += bx * W2s[k * 64 + 2 * lane + 1];
        ox += by * W2s[(k + 1) * 64 + 2 * lane];
        oy += by * W2s[(k + 1) * 64 + 2 * lane + 1];
    }
    // relu + residual => x2 (registers only)
    float x2x = fmaxf(ox, 0.0f) + hv0.x;
    float x2y = fmaxf(oy, 0.0f) + hv0.y;

    // fused projection 64 -> 10 (butterfly reduction per output)
    float pj = 0.0f;
    for (int j = 0; j < 10; j++) {
        float pv = x2x * W3s[(2 * lane) * 10 + j] + x2y * W3s[(2 * lane + 1) * 10 + j];
        for (int off = 16; off; off >>= 1) pv += __shfl_xor_sync(FULL, pv, off);
        if (lane == j) pj = pv;
    }
    if (lane < 10) g_p[v * 10 + lane] = pj;
}

// ---------------- layer 3: agg(p)[10] + b3 -> log_softmax -> out ----------------
__global__ void k_layer3(const float* __restrict__ b3, float* __restrict__ out) {
    int v = (blockIdx.x * blockDim.x + threadIdx.x) >> 5;
    int lane = threadIdx.x & 31;
    if (v >= N_NODES) return;

    float di = g_dinv[v];
    float d2 = di * di;
    float a = (lane < 10) ? d2 * g_p[v * 10 + lane] : 0.0f;
    int beg = g_rowptr[v], end = g_rowptr[v + 1];
    for (int e0 = beg; e0 < end; e0 += 32) {
        int idx = e0 + lane;
        int c = 0; float w = 0.0f;
        if (idx < end) { c = g_col[idx]; w = g_nw[idx]; }
        int m = end - e0; if (m > 32) m = 32;
        for (int t = 0; t < m; t++) {
            int cc = __shfl_sync(FULL, c, t);
            float ww = __shfl_sync(FULL, w, t);
            if (lane < 10) a += ww * g_p[cc * 10 + lane];
        }
    }
    float z = (lane < 10) ? a + b3[lane] : -INFINITY;
    float m = z;
    for (int off = 16; off; off >>= 1) m = fmaxf(m, __shfl_xor_sync(FULL, m, off));
    float ex = (lane < 10) ? expf(z - m) : 0.0f;
    float s = ex;
    for (int off = 16; off; off >>= 1) s += __shfl_xor_sync(FULL, s, off);
    if (lane < 10) out[v * 10 + lane] = z - m - logf(s);
}

extern "C" void kernel_launch(void* const* d_in, const int* in_sizes, int n_in,
                              void* d_out, int out_size) {
    const float* x  = (const float*)d_in[0];
    const int*   ei = (const int*)d_in[1];
    const float* W1 = (const float*)d_in[2];
    const float* b1 = (const float*)d_in[3];
    const float* W2 = (const float*)d_in[4];
    const float* b2 = (const float*)d_in[5];
    const float* W3 = (const float*)d_in[6];
    const float* b3 = (const float*)d_in[7];
    float* out = (float*)d_out;

    const int TB = 256;
    int nodeBlocks = (N_NODES + TB - 1) / TB;
    int edgeBlocks = (N_EDGES + TB - 1) / TB;
    int warpNodeBlocks = (N_NODES * 32 + TB - 1) / TB;  // warp per node

    k_zero<<<nodeBlocks, TB>>>();
    k_hist<<<edgeBlocks, TB>>>(ei);
    k_scan<<<1, 1024>>>();
    k_scatter<<<edgeBlocks, TB>>>(ei);
    k_layer1<<<warpNodeBlocks, TB>>>(x, W1, b1);
    k_layer2<<<warpNodeBlocks, TB>>>(W2, b2, W3);
    k_layer3<<<warpNodeBlocks, TB>>>(b3, out);
}

// round 3
// speedup vs baseline: 1.8154x; 1.8154x over previous
#include <cuda_runtime.h>
#include <math.h>

#define N_NODES 100000
#define N_EDGES 1600000
#define FULL 0xffffffffu
#define NB_SCAN 391   // ceil(100000/256)

// ---- scratch (static device globals; no allocation allowed) ----
__device__ int   g_count[N_NODES];          // histogram, then scatter cursor
__device__ int   g_rowptr[N_NODES + 1];     // CSR row pointers (by dst)
__device__ float g_dinv[N_NODES];           // deg^-1/2 (deg includes self loop)
__device__ __align__(16) int2  g_ew[N_EDGES];        // {src, norm-bits} fused record
__device__ int   g_bsum[NB_SCAN];           // per-block count sums
__device__ int   g_bpre[NB_SCAN];           // exclusive prefix of block sums
__device__ __align__(16) float g_x0[N_NODES * 16];   // x padded to stride 16
__device__ __align__(16) float g_x1[N_NODES * 64];   // layer-1 output
__device__ __align__(16) float g_p[N_NODES * 16];    // x2 @ W3 logits, stride 16

// ---------------- CSR build ----------------
__global__ void k_zero() {
    int i = blockIdx.x * blockDim.x + threadIdx.x;
    if (i < N_NODES) g_count[i] = 0;
}

__global__ void k_hist(const int* __restrict__ ei) {
    int e4 = blockIdx.x * blockDim.x + threadIdx.x;
    if (e4 < N_EDGES / 4) {
        int4 d = ((const int4*)(ei + N_EDGES))[e4];
        atomicAdd(&g_count[d.x], 1);
        atomicAdd(&g_count[d.y], 1);
        atomicAdd(&g_count[d.z], 1);
        atomicAdd(&g_count[d.w], 1);
    }
}

// pad x [N,13] -> g_x0 [N,16] (aligned gathers later)
__global__ void k_padx(const float* __restrict__ x) {
    int i = blockIdx.x * blockDim.x + threadIdx.x;
    if (i < N_NODES * 16) {
        int v = i >> 4, f = i & 15;
        g_x0[i] = (f < 13) ? x[v * 13 + f] : 0.0f;
    }
}

// per-256-chunk sums of g_count
__global__ void k_blocksum() {
    __shared__ int s[256];
    int i = blockIdx.x * 256 + threadIdx.x;
    int c = (i < N_NODES) ? g_count[i] : 0;
    s[threadIdx.x] = c;
    __syncthreads();
    for (int off = 128; off; off >>= 1) {
        if (threadIdx.x < off) s[threadIdx.x] += s[threadIdx.x + off];
        __syncthreads();
    }
    if (threadIdx.x == 0) g_bsum[blockIdx.x] = s[0];
}

// single small block: exclusive scan of 391 block sums
__global__ void k_scanb() {
    __shared__ int s[512];
    int tid = threadIdx.x;
    int v = (tid < NB_SCAN) ? g_bsum[tid] : 0;
    s[tid] = v;
    __syncthreads();
    for (int off = 1; off < 512; off <<= 1) {
        int t = (tid >= off) ? s[tid - off] : 0;
        __syncthreads();
        s[tid] += t;
        __syncthreads();
    }
    if (tid < NB_SCAN) g_bpre[tid] = s[tid] - v;
}

// per-element rowptr + dinv + cursor reset
__global__ void k_writerp() {
    __shared__ int s[256];
    int tid = threadIdx.x;
    int i = blockIdx.x * 256 + tid;
    int c = (i < N_NODES) ? g_count[i] : 0;
    s[tid] = c;
    __syncthreads();
    for (int off = 1; off < 256; off <<= 1) {
        int t = (tid >= off) ? s[tid - off] : 0;
        __syncthreads();
        s[tid] += t;
        __syncthreads();
    }
    if (i < N_NODES) {
        g_rowptr[i] = g_bpre[blockIdx.x] + s[tid] - c;
        g_dinv[i] = rsqrtf((float)c + 1.0f);
        g_count[i] = 0;
    }
    if (i == 0) g_rowptr[N_NODES] = N_EDGES;
}

__global__ void k_scatter(const int* __restrict__ ei) {
    int e2 = blockIdx.x * blockDim.x + threadIdx.x;
    if (e2 < N_EDGES / 2) {
        int2 ss = ((const int2*)ei)[e2];
        int2 dd = ((const int2*)(ei + N_EDGES))[e2];
        float nw0 = g_dinv[ss.x] * g_dinv[dd.x];
        int p0 = g_rowptr[dd.x] + atomicAdd(&g_count[dd.x], 1);
        g_ew[p0] = make_int2(ss.x, __float_as_int(nw0));
        float nw1 = g_dinv[ss.y] * g_dinv[dd.y];
        int p1 = g_rowptr[dd.y] + atomicAdd(&g_count[dd.y], 1);
        g_ew[p1] = make_int2(ss.y, __float_as_int(nw1));
    }
}

// ---------------- layer 1: agg(x)[13] -> @W1 +b1 -> relu -> x1[64] ----------------
// warp per node; two 16-lane halves each handle one edge per t-iteration
__global__ void k_layer1(const float* __restrict__ W1,
                         const float* __restrict__ b1) {
    __shared__ float W1s[13 * 64];
    __shared__ float b1s[64];
    for (int i = threadIdx.x; i < 13 * 64; i += blockDim.x) W1s[i] = W1[i];
    for (int i = threadIdx.x; i < 64; i += blockDim.x) b1s[i] = b1[i];
    __syncthreads();

    int v = (blockIdx.x * blockDim.x + threadIdx.x) >> 5;
    int lane = threadIdx.x & 31;
    int half = lane >> 4, hl = lane & 15;
    if (v >= N_NODES) return;

    float di = g_dinv[v];
    float a = 0.0f;
    if (half == 0 && hl < 13) a = di * di * g_x0[v * 16 + hl];

    int beg = g_rowptr[v], end = g_rowptr[v + 1];
    for (int e0 = beg; e0 < end; e0 += 32) {
        int idx = e0 + lane;
        int2 ew = (idx < end) ? g_ew[idx] : make_int2(0, 0);
        int m = end - e0; if (m > 32) m = 32;
        for (int t = 0; t < m; t += 2) {
            int src = t + half;  // <= 31
            int cc = __shfl_sync(FULL, ew.x, src);
            float ww = __int_as_float(__shfl_sync(FULL, ew.y, src));
            if (hl < 13) a += ww * g_x0[cc * 16 + hl];
        }
    }
    a += __shfl_xor_sync(FULL, a, 16);  // combine halves

    // GEMM 13 -> 64 (2 outputs per lane)
    float ox = b1s[2 * lane], oy = b1s[2 * lane + 1];
#pragma unroll
    for (int k = 0; k < 13; k++) {
        float av = __shfl_sync(FULL, a, k);
        ox += av * W1s[k * 64 + 2 * lane];
        oy += av * W1s[k * 64 + 2 * lane + 1];
    }
    ((float2*)(g_x1 + v * 64))[lane] = make_float2(fmaxf(ox, 0.0f), fmaxf(oy, 0.0f));
}

// ---------------- layer 2: agg(x1)[64] -> @W2 +b2 relu + x1 -> @W3 -> p[10] ----------------
// warp per node; two 16-lane halves, float4 per lane (full 256B row per half)
__global__ void k_layer2(const float* __restrict__ W2,
                         const float* __restrict__ b2,
                         const float* __restrict__ W3) {
    __shared__ float W2s[64 * 64];
    __shared__ float b2s[64];
    __shared__ float W3s[64 * 10];
    for (int i = threadIdx.x; i < 64 * 64; i += blockDim.x) W2s[i] = W2[i];
    for (int i = threadIdx.x; i < 64; i += blockDim.x) b2s[i] = b2[i];
    for (int i = threadIdx.x; i < 64 * 10; i += blockDim.x) W3s[i] = W3[i];
    __syncthreads();

    int v = (blockIdx.x * blockDim.x + threadIdx.x) >> 5;
    int lane = threadIdx.x & 31;
    int half = lane >> 4, hl = lane & 15;
    if (v >= N_NODES) return;

    float di = g_dinv[v];
    float d2 = di * di;
    float4 acc = make_float4(0.f, 0.f, 0.f, 0.f);
    if (half == 0) {
        float4 rv = ((const float4*)(g_x1 + v * 64))[hl];
        acc = make_float4(d2 * rv.x, d2 * rv.y, d2 * rv.z, d2 * rv.w);
    }

    int beg = g_rowptr[v], end = g_rowptr[v + 1];
    for (int e0 = beg; e0 < end; e0 += 32) {
        int idx = e0 + lane;
        int2 ew = (idx < end) ? g_ew[idx] : make_int2(0, 0);
        int m = end - e0; if (m > 32) m = 32;
        for (int t = 0; t < m; t += 2) {
            int src = t + half;  // <= 31
            int cc = __shfl_sync(FULL, ew.x, src);
            float ww = __int_as_float(__shfl_sync(FULL, ew.y, src));
            float4 hv = ((const float4*)(g_x1 + cc * 64))[hl];
            acc.x += ww * hv.x; acc.y += ww * hv.y;
            acc.z += ww * hv.z; acc.w += ww * hv.w;
        }
    }
    // combine halves: all lanes end with combined float4 for slot hl
    acc.x += __shfl_xor_sync(FULL, acc.x, 16);
    acc.y += __shfl_xor_sync(FULL, acc.y, 16);
    acc.z += __shfl_xor_sync(FULL, acc.z, 16);
    acc.w += __shfl_xor_sync(FULL, acc.w, 16);

    // GEMM 64 -> 64; feature k lives in lane k>>2, component k&3
    float ox = b2s[2 * lane], oy = b2s[2 * lane + 1];
#pragma unroll
    for (int k = 0; k < 64; k++) {
        float comp = (k & 3) == 0 ? acc.x : (k & 3) == 1 ? acc.y : (k & 3) == 2 ? acc.z : acc.w;
        float av = __shfl_sync(FULL, comp, k >> 2);
        ox += av * W2s[k * 64 + 2 * lane];
        oy += av * W2s[k * 64 + 2 * lane + 1];
    }
    // relu + residual (x2 stays in registers)
    float2 r = ((const float2*)(g_x1 + v * 64))[lane];
    float x2x = fmaxf(ox, 0.0f) + r.x;
    float x2y = fmaxf(oy, 0.0f) + r.y;

    // fused projection 64 -> 10
    float pj = 0.0f;
#pragma unroll
    for (int j = 0; j < 10; j++) {
        float pv = x2x * W3s[(2 * lane) * 10 + j] + x2y * W3s[(2 * lane + 1) * 10 + j];
        for (int off = 16; off; off >>= 1) pv += __shfl_xor_sync(FULL, pv, off);
        if (lane == j) pj = pv;
    }
    if (lane < 10) g_p[v * 16 + lane] = pj;
}

// ---------------- layer 3: agg(p)[10] + b3 -> log_softmax -> out ----------------
// warp per node; three 10-lane groups each handle one edge per t-iteration
__global__ void k_layer3(const float* __restrict__ b3, float* __restrict__ out) {
    int v = (blockIdx.x * blockDim.x + threadIdx.x) >> 5;
    int lane = threadIdx.x & 31;
    int group = lane / 10;            // 0,1,2 for lanes<30; 3 for 30,31
    int gl = lane - group * 10;
    if (v >= N_NODES) return;

    float di = g_dinv[v];
    float d2 = di * di;
    float a = (lane < 10) ? d2 * g_p[v * 16 + lane] : 0.0f;

    int beg = g_rowptr[v], end = g_rowptr[v + 1];
    for (int e0 = beg; e0 < end; e0 += 32) {
        int idx = e0 + lane;
        int2 ew = (idx < end) ? g_ew[idx] : make_int2(0, 0);
        int m = end - e0; if (m > 32) m = 32;
        for (int t = 0; t < m; t += 3) {
            int srcu = t + group;           // may be >= 32 for group 2
            int s2 = srcu < 31 ? srcu : 31; // clamp for shfl validity
            int cc = __shfl_sync(FULL, ew.x, s2);
            float ww = __int_as_float(__shfl_sync(FULL, ew.y, s2));
            if (srcu < m && group < 3) a += ww * g_p[cc * 16 + gl];
        }
    }
    // combine: feature f partials live in lanes f, f+10, f+20
    int i1 = lane + 10 < 32 ? lane + 10 : 31;
    int i2 = lane + 20 < 32 ? lane + 20 : 31;
    float a1 = __shfl_sync(FULL, a, i1);
    float a2 = __shfl_sync(FULL, a, i2);

    float z = (lane < 10) ? a + a1 + a2 + b3[lane] : -INFINITY;
    float mx = z;
    for (int off = 16; off; off >>= 1) mx = fmaxf(mx, __shfl_xor_sync(FULL, mx, off));
    float ex = (lane < 10) ? expf(z - mx) : 0.0f;
    float s = ex;
    for (int off = 16; off; off >>= 1) s += __shfl_xor_sync(FULL, s, off);
    if (lane < 10) out[v * 10 + lane] = z - mx - logf(s);
}

extern "C" void kernel_launch(void* const* d_in, const int* in_sizes, int n_in,
                              void* d_out, int out_size) {
    const float* x  = (const float*)d_in[0];
    const int*   ei = (const int*)d_in[1];
    const float* W1 = (const float*)d_in[2];
    const float* b1 = (const float*)d_in[3];
    const float* W2 = (const float*)d_in[4];
    const float* b2 = (const float*)d_in[5];
    const float* W3 = (const float*)d_in[6];
    const float* b3 = (const float*)d_in[7];
    float* out = (float*)d_out;

    const int TB = 256;
    int nodeBlocks  = (N_NODES + TB - 1) / TB;
    int hist4Blocks = (N_EDGES / 4 + TB - 1) / TB;
    int scat2Blocks = (N_EDGES / 2 + TB - 1) / TB;
    int padBlocks   = (N_NODES * 16 + TB - 1) / TB;
    int warpNodeBlocks = (N_NODES * 32 + TB - 1) / TB;

    k_zero<<<nodeBlocks, TB>>>();
    k_hist<<<hist4Blocks, TB>>>(ei);
    k_padx<<<padBlocks, TB>>>(x);
    k_blocksum<<<NB_SCAN, TB>>>();
    k_scanb<<<1, 512>>>();
    k_writerp<<<NB_SCAN, TB>>>();
    k_scatter<<<scat2Blocks, TB>>>(ei);
    k_layer1<<<warpNodeBlocks, TB>>>(W1, b1);
    k_layer2<<<warpNodeBlocks, TB>>>(W2, b2, W3);
    k_layer3<<<warpNodeBlocks, TB>>>(b3, out);
}

// round 4
// speedup vs baseline: 1.8291x; 1.0075x over previous
#include <cuda_runtime.h>
#include <math.h>

#define N_NODES 100000
#define N_EDGES 1600000
#define FULL 0xffffffffu
#define NB_SCAN 391   // ceil(100000/256)

// ---- scratch (static device globals; no allocation allowed) ----
__device__ int   g_count[N_NODES];          // histogram, then absolute scatter cursor
__device__ int   g_rowptr[N_NODES + 1];     // CSR row pointers (by dst)
__device__ float g_dinv[N_NODES];           // deg^-1/2 (deg includes self loop)
__device__ __align__(16) int2  g_ew[N_EDGES];        // {src, norm-bits}
__device__ int   g_bsum[NB_SCAN];
__device__ int   g_bpre[NB_SCAN];
__device__ __align__(16) float g_x0[N_NODES * 16];   // x padded to stride 16
__device__ __align__(16) float g_x1[N_NODES * 64];   // layer-1 output
__device__ __align__(16) float g_p[N_NODES * 16];    // logits, stride 16 (pad stays 0)

// ---------------- CSR build ----------------
__global__ void k_zero() {
    int i = blockIdx.x * blockDim.x + threadIdx.x;
    if (i < N_NODES) g_count[i] = 0;
}

__global__ void k_hist(const int* __restrict__ ei) {
    int e4 = blockIdx.x * blockDim.x + threadIdx.x;
    if (e4 < N_EDGES / 4) {
        int4 d = ((const int4*)(ei + N_EDGES))[e4];
        atomicAdd(&g_count[d.x], 1);
        atomicAdd(&g_count[d.y], 1);
        atomicAdd(&g_count[d.z], 1);
        atomicAdd(&g_count[d.w], 1);
    }
}

__global__ void k_padx(const float* __restrict__ x) {
    int i = blockIdx.x * blockDim.x + threadIdx.x;
    if (i < N_NODES * 16) {
        int v = i >> 4, f = i & 15;
        g_x0[i] = (f < 13) ? x[v * 13 + f] : 0.0f;
    }
}

__global__ void k_blocksum() {
    __shared__ int s[256];
    int i = blockIdx.x * 256 + threadIdx.x;
    int c = (i < N_NODES) ? g_count[i] : 0;
    s[threadIdx.x] = c;
    __syncthreads();
    for (int off = 128; off; off >>= 1) {
        if (threadIdx.x < off) s[threadIdx.x] += s[threadIdx.x + off];
        __syncthreads();
    }
    if (threadIdx.x == 0) g_bsum[blockIdx.x] = s[0];
}

__global__ void k_scanb() {
    __shared__ int s[512];
    int tid = threadIdx.x;
    int v = (tid < NB_SCAN) ? g_bsum[tid] : 0;
    s[tid] = v;
    __syncthreads();
    for (int off = 1; off < 512; off <<= 1) {
        int t = (tid >= off) ? s[tid - off] : 0;
        __syncthreads();
        s[tid] += t;
        __syncthreads();
    }
    if (tid < NB_SCAN) g_bpre[tid] = s[tid] - v;
}

// rowptr + dinv + cursor init (cursor = absolute rowptr)
__global__ void k_writerp() {
    __shared__ int s[256];
    int tid = threadIdx.x;
    int i = blockIdx.x * 256 + tid;
    int c = (i < N_NODES) ? g_count[i] : 0;
    s[tid] = c;
    __syncthreads();
    for (int off = 1; off < 256; off <<= 1) {
        int t = (tid >= off) ? s[tid - off] : 0;
        __syncthreads();
        s[tid] += t;
        __syncthreads();
    }
    if (i < N_NODES) {
        int rp = g_bpre[blockIdx.x] + s[tid] - c;
        g_rowptr[i] = rp;
        g_dinv[i] = rsqrtf((float)c + 1.0f);
        g_count[i] = rp;  // absolute cursor for scatter
    }
    if (i == 0) g_rowptr[N_NODES] = N_EDGES;
}

__global__ void k_scatter(const int* __restrict__ ei) {
    int e2 = blockIdx.x * blockDim.x + threadIdx.x;
    if (e2 < N_EDGES / 2) {
        int2 ss = ((const int2*)ei)[e2];
        int2 dd = ((const int2*)(ei + N_EDGES))[e2];
        float nw0 = g_dinv[ss.x] * g_dinv[dd.x];
        int p0 = atomicAdd(&g_count[dd.x], 1);
        g_ew[p0] = make_int2(ss.x, __float_as_int(nw0));
        float nw1 = g_dinv[ss.y] * g_dinv[dd.y];
        int p1 = atomicAdd(&g_count[dd.y], 1);
        g_ew[p1] = make_int2(ss.y, __float_as_int(nw1));
    }
}

// ---------------- layer 1: agg(x)[13] -> @W1 +b1 -> relu -> x1[64] ----------------
// warp/node; 8 edges per iteration (4 lanes x float4 per edge), fixed-trip chunks
__global__ void k_layer1(const float* __restrict__ W1,
                         const float* __restrict__ b1) {
    __shared__ float W1s[13 * 64];
    __shared__ float b1s[64];
    __shared__ int2 sew[8][32];
    for (int i = threadIdx.x; i < 13 * 64; i += blockDim.x) W1s[i] = W1[i];
    for (int i = threadIdx.x; i < 64; i += blockDim.x) b1s[i] = b1[i];
    __syncthreads();

    int warp = threadIdx.x >> 5;
    int v = (blockIdx.x * blockDim.x + threadIdx.x) >> 5;
    int lane = threadIdx.x & 31;
    if (v >= N_NODES) return;
    int grp = lane >> 2;   // edge subgroup 0..7
    int q   = lane & 3;    // feature quad 0..3

    float di = g_dinv[v];
    float4 acc = make_float4(0.f, 0.f, 0.f, 0.f);
    if (grp == 0) {
        float4 rv = ((const float4*)(g_x0 + v * 16))[q];
        float d2 = di * di;
        acc = make_float4(d2 * rv.x, d2 * rv.y, d2 * rv.z, d2 * rv.w);
    }

    int beg = g_rowptr[v], end = g_rowptr[v + 1];
    for (int e0 = beg; e0 < end; e0 += 32) {
        int idx = e0 + lane;
        sew[warp][lane] = (idx < end) ? g_ew[idx] : make_int2(v, 0);
        __syncwarp();
#pragma unroll
        for (int t = 0; t < 4; t++) {
            int2 e = sew[warp][t * 8 + grp];
            float ww = __int_as_float(e.y);
            float4 hv = ((const float4*)(g_x0 + e.x * 16))[q];
            acc.x += ww * hv.x; acc.y += ww * hv.y;
            acc.z += ww * hv.z; acc.w += ww * hv.w;
        }
        __syncwarp();
    }
    // combine 8 edge subgroups (lanes sharing the same quad q)
#pragma unroll
    for (int off = 4; off <= 16; off <<= 1) {
        acc.x += __shfl_xor_sync(FULL, acc.x, off);
        acc.y += __shfl_xor_sync(FULL, acc.y, off);
        acc.z += __shfl_xor_sync(FULL, acc.z, off);
        acc.w += __shfl_xor_sync(FULL, acc.w, off);
    }
    // GEMM 13 -> 64 (2 outputs per lane); feature k: quad k>>2, comp k&3
    float ox = b1s[2 * lane], oy = b1s[2 * lane + 1];
#pragma unroll
    for (int k = 0; k < 13; k++) {
        float comp = (k & 3) == 0 ? acc.x : (k & 3) == 1 ? acc.y : (k & 3) == 2 ? acc.z : acc.w;
        float av = __shfl_sync(FULL, comp, k >> 2);
        ox += av * W1s[k * 64 + 2 * lane];
        oy += av * W1s[k * 64 + 2 * lane + 1];
    }
    ((float2*)(g_x1 + v * 64))[lane] = make_float2(fmaxf(ox, 0.0f), fmaxf(oy, 0.0f));
}

// ---------------- layer 2: agg(x1)[64] -> @W2 +b2 relu + x1 -> @W3 -> p[10] ----------------
// warp/node; 2 edges per iteration (16 lanes x float4), fixed-trip chunks
__global__ void k_layer2(const float* __restrict__ W2,
                         const float* __restrict__ b2,
                         const float* __restrict__ W3) {
    __shared__ float W2s[64 * 64];
    __shared__ float b2s[64];
    __shared__ float W3s[64 * 10];
    __shared__ int2 sew[8][32];
    for (int i = threadIdx.x; i < 64 * 64; i += blockDim.x) W2s[i] = W2[i];
    for (int i = threadIdx.x; i < 64; i += blockDim.x) b2s[i] = b2[i];
    for (int i = threadIdx.x; i < 64 * 10; i += blockDim.x) W3s[i] = W3[i];
    __syncthreads();

    int warp = threadIdx.x >> 5;
    int v = (blockIdx.x * blockDim.x + threadIdx.x) >> 5;
    int lane = threadIdx.x & 31;
    if (v >= N_NODES) return;
    int half = lane >> 4, hl = lane & 15;

    float di = g_dinv[v];
    float4 acc = make_float4(0.f, 0.f, 0.f, 0.f);
    if (half == 0) {
        float4 rv = ((const float4*)(g_x1 + v * 64))[hl];
        float d2 = di * di;
        acc = make_float4(d2 * rv.x, d2 * rv.y, d2 * rv.z, d2 * rv.w);
    }

    int beg = g_rowptr[v], end = g_rowptr[v + 1];
    for (int e0 = beg; e0 < end; e0 += 32) {
        int idx = e0 + lane;
        sew[warp][lane] = (idx < end) ? g_ew[idx] : make_int2(v, 0);
        __syncwarp();
#pragma unroll
        for (int t = 0; t < 16; t++) {
            int2 e = sew[warp][t * 2 + half];
            float ww = __int_as_float(e.y);
            float4 hv = ((const float4*)(g_x1 + e.x * 64))[hl];
            acc.x += ww * hv.x; acc.y += ww * hv.y;
            acc.z += ww * hv.z; acc.w += ww * hv.w;
        }
        __syncwarp();
    }
    acc.x += __shfl_xor_sync(FULL, acc.x, 16);
    acc.y += __shfl_xor_sync(FULL, acc.y, 16);
    acc.z += __shfl_xor_sync(FULL, acc.z, 16);
    acc.w += __shfl_xor_sync(FULL, acc.w, 16);

    // GEMM 64 -> 64; feature k lives in lane k>>2, component k&3
    float ox = b2s[2 * lane], oy = b2s[2 * lane + 1];
#pragma unroll
    for (int k = 0; k < 64; k++) {
        float comp = (k & 3) == 0 ? acc.x : (k & 3) == 1 ? acc.y : (k & 3) == 2 ? acc.z : acc.w;
        float av = __shfl_sync(FULL, comp, k >> 2);
        ox += av * W2s[k * 64 + 2 * lane];
        oy += av * W2s[k * 64 + 2 * lane + 1];
    }
    // relu + residual (x2 stays in registers)
    float2 r = ((const float2*)(g_x1 + v * 64))[lane];
    float x2x = fmaxf(ox, 0.0f) + r.x;
    float x2y = fmaxf(oy, 0.0f) + r.y;

    // fused projection 64 -> 10
    float pj = 0.0f;
#pragma unroll
    for (int j = 0; j < 10; j++) {
        float pv = x2x * W3s[(2 * lane) * 10 + j] + x2y * W3s[(2 * lane + 1) * 10 + j];
        for (int off = 16; off; off >>= 1) pv += __shfl_xor_sync(FULL, pv, off);
        if (lane == j) pj = pv;
    }
    if (lane < 16) g_p[v * 16 + lane] = (lane < 10) ? pj : 0.0f;
}

// ---------------- layer 3: agg(p)[10] + b3 -> log_softmax -> out ----------------
// warp/node; 4 edges per iteration (8 lanes x float2), fixed-trip chunks
__global__ void k_layer3(const float* __restrict__ b3, float* __restrict__ out) {
    __shared__ int2 sew[8][32];
    int warp = threadIdx.x >> 5;
    int v = (blockIdx.x * blockDim.x + threadIdx.x) >> 5;
    int lane = threadIdx.x & 31;
    if (v >= N_NODES) return;
    int grp = lane >> 3;   // edge subgroup 0..3
    int fl  = lane & 7;    // feature pair 0..7 (pairs 5..7 are zero padding)

    float di = g_dinv[v];
    float2 acc = make_float2(0.f, 0.f);
    if (grp == 0) {
        float2 rv = ((const float2*)(g_p + v * 16))[fl];
        float d2 = di * di;
        acc = make_float2(d2 * rv.x, d2 * rv.y);
    }

    int beg = g_rowptr[v], end = g_rowptr[v + 1];
    for (int e0 = beg; e0 < end; e0 += 32) {
        int idx = e0 + lane;
        sew[warp][lane] = (idx < end) ? g_ew[idx] : make_int2(v, 0);
        __syncwarp();
#pragma unroll
        for (int t = 0; t < 8; t++) {
            int2 e = sew[warp][t * 4 + grp];
            float ww = __int_as_float(e.y);
            float2 hv = ((const float2*)(g_p + e.x * 16))[fl];
            acc.x += ww * hv.x; acc.y += ww * hv.y;
        }
        __syncwarp();
    }
    acc.x += __shfl_xor_sync(FULL, acc.x, 8);
    acc.y += __shfl_xor_sync(FULL, acc.y, 8);
    acc.x += __shfl_xor_sync(FULL, acc.x, 16);
    acc.y += __shfl_xor_sync(FULL, acc.y, 16);
    // all lanes now hold summed pair (lane&7); fan out to lane-per-feature
    float pa = __shfl_sync(FULL, acc.x, lane >> 1);
    float pb = __shfl_sync(FULL, acc.y, lane >> 1);

    float z = (lane < 10) ? ((lane & 1) ? pb : pa) + b3[lane] : -INFINITY;
    float mx = z;
    for (int off = 16; off; off >>= 1) mx = fmaxf(mx, __shfl_xor_sync(FULL, mx, off));
    float ex = (lane < 10) ? expf(z - mx) : 0.0f;
    float s = ex;
    for (int off = 16; off; off >>= 1) s += __shfl_xor_sync(FULL, s, off);
    if (lane < 10) out[v * 10 + lane] = z - mx - logf(s);
}

extern "C" void kernel_launch(void* const* d_in, const int* in_sizes, int n_in,
                              void* d_out, int out_size) {
    const float* x  = (const float*)d_in[0];
    const int*   ei = (const int*)d_in[1];
    const float* W1 = (const float*)d_in[2];
    const float* b1 = (const float*)d_in[3];
    const float* W2 = (const float*)d_in[4];
    const float* b2 = (const float*)d_in[5];
    const float* W3 = (const float*)d_in[6];
    const float* b3 = (const float*)d_in[7];
    float* out = (float*)d_out;

    const int TB = 256;
    int nodeBlocks  = (N_NODES + TB - 1) / TB;
    int hist4Blocks = (N_EDGES / 4 + TB - 1) / TB;
    int scat2Blocks = (N_EDGES / 2 + TB - 1) / TB;
    int padBlocks   = (N_NODES * 16 + TB - 1) / TB;
    int warpNodeBlocks = (N_NODES * 32 + TB - 1) / TB;

    k_zero<<<nodeBlocks, TB>>>();
    k_hist<<<hist4Blocks, TB>>>(ei);
    k_padx<<<padBlocks, TB>>>(x);
    k_blocksum<<<NB_SCAN, TB>>>();
    k_scanb<<<1, 512>>>();
    k_writerp<<<NB_SCAN, TB>>>();
    k_scatter<<<scat2Blocks, TB>>>(ei);
    k_layer1<<<warpNodeBlocks, TB>>>(W1, b1);
    k_layer2<<<warpNodeBlocks, TB>>>(W2, b2, W3);
    k_layer3<<<warpNodeBlocks, TB>>>(b3, out);
}

// round 5
// speedup vs baseline: 2.0985x; 1.1473x over previous
#include <cuda_runtime.h>
#include <cuda_fp16.h>
#include <math.h>

#define N_NODES 100000
#define N_EDGES 1600000
#define FULL 0xffffffffu
#define NB_SCAN 391   // ceil(100000/256)

// ---- scratch (static device globals; no allocation allowed) ----
__device__ int   g_count[N_NODES];          // histogram, then absolute scatter cursor
__device__ int   g_rowptr[N_NODES + 1];     // CSR row pointers (by dst)
__device__ float g_dinv[N_NODES];           // deg^-1/2 (deg includes self loop)
__device__ int   g_col[N_EDGES];            // CSR src indices (weight folded into features)
__device__ int   g_bsum[NB_SCAN];
__device__ int   g_bpre[NB_SCAN];
__device__ __align__(16) __half g_x0h[N_NODES * 16];  // dinv[v]*x[v], 13 used, fp16
__device__ __align__(16) __half g_x1h[N_NODES * 64];  // dinv[v]*x1[v], fp16
__device__ __align__(16) __half g_ph [N_NODES * 16];  // dinv[v]*p[v], 10 used, fp16

// ---------------- CSR build ----------------
__global__ void k_zero() {
    int i = blockIdx.x * blockDim.x + threadIdx.x;
    if (i < N_NODES) g_count[i] = 0;
}

__global__ void k_hist(const int* __restrict__ ei) {
    int e4 = blockIdx.x * blockDim.x + threadIdx.x;
    if (e4 < N_EDGES / 4) {
        int4 d = ((const int4*)(ei + N_EDGES))[e4];
        atomicAdd(&g_count[d.x], 1);
        atomicAdd(&g_count[d.y], 1);
        atomicAdd(&g_count[d.z], 1);
        atomicAdd(&g_count[d.w], 1);
    }
}

__global__ void k_blocksum() {
    __shared__ int s[256];
    int i = blockIdx.x * 256 + threadIdx.x;
    int c = (i < N_NODES) ? g_count[i] : 0;
    s[threadIdx.x] = c;
    __syncthreads();
    for (int off = 128; off; off >>= 1) {
        if (threadIdx.x < off) s[threadIdx.x] += s[threadIdx.x + off];
        __syncthreads();
    }
    if (threadIdx.x == 0) g_bsum[blockIdx.x] = s[0];
}

__global__ void k_scanb() {
    __shared__ int s[512];
    int tid = threadIdx.x;
    int v = (tid < NB_SCAN) ? g_bsum[tid] : 0;
    s[tid] = v;
    __syncthreads();
    for (int off = 1; off < 512; off <<= 1) {
        int t = (tid >= off) ? s[tid - off] : 0;
        __syncthreads();
        s[tid] += t;
        __syncthreads();
    }
    if (tid < NB_SCAN) g_bpre[tid] = s[tid] - v;
}

__global__ void k_writerp() {
    __shared__ int s[256];
    int tid = threadIdx.x;
    int i = blockIdx.x * 256 + tid;
    int c = (i < N_NODES) ? g_count[i] : 0;
    s[tid] = c;
    __syncthreads();
    for (int off = 1; off < 256; off <<= 1) {
        int t = (tid >= off) ? s[tid - off] : 0;
        __syncthreads();
        s[tid] += t;
        __syncthreads();
    }
    if (i < N_NODES) {
        int rp = g_bpre[blockIdx.x] + s[tid] - c;
        g_rowptr[i] = rp;
        g_dinv[i] = rsqrtf((float)c + 1.0f);
        g_count[i] = rp;  // absolute cursor for scatter
    }
    if (i == 0) g_rowptr[N_NODES] = N_EDGES;
}

// pad + pre-scale x: g_x0h[v] = dinv[v] * x[v] (fp16, 16-wide)
__global__ void k_padx(const float* __restrict__ x) {
    int v = blockIdx.x * blockDim.x + threadIdx.x;
    if (v >= N_NODES) return;
    float di = g_dinv[v];
    __half2* o = (__half2*)(g_x0h + v * 16);
#pragma unroll
    for (int i = 0; i < 8; i++) {
        float a = (2 * i < 13)     ? di * x[v * 13 + 2 * i]     : 0.0f;
        float b = (2 * i + 1 < 13) ? di * x[v * 13 + 2 * i + 1] : 0.0f;
        o[i] = __floats2half2_rn(a, b);
    }
}

__global__ void k_scatter(const int* __restrict__ ei) {
    int e2 = blockIdx.x * blockDim.x + threadIdx.x;
    if (e2 < N_EDGES / 2) {
        int2 ss = ((const int2*)ei)[e2];
        int2 dd = ((const int2*)(ei + N_EDGES))[e2];
        int p0 = atomicAdd(&g_count[dd.x], 1);
        g_col[p0] = ss.x;
        int p1 = atomicAdd(&g_count[dd.y], 1);
        g_col[p1] = ss.y;
    }
}

// helper: accumulate one fp16x8 (int4) row chunk into 8 fp32 accs
__device__ __forceinline__ void acc8(float* acc, const __half* base) {
    int4 raw = *reinterpret_cast<const int4*>(base);
    float2 f0 = __half22float2(*(__half2*)&raw.x);
    float2 f1 = __half22float2(*(__half2*)&raw.y);
    float2 f2 = __half22float2(*(__half2*)&raw.z);
    float2 f3 = __half22float2(*(__half2*)&raw.w);
    acc[0] += f0.x; acc[1] += f0.y; acc[2] += f1.x; acc[3] += f1.y;
    acc[4] += f2.x; acc[5] += f2.y; acc[6] += f3.x; acc[7] += f3.y;
}

// ---------------- layer 1: agg(x0')[16h] -> *dinv -> @W1 +b1 -> relu -> *dinv -> x1h ----------------
// warp/node; 2 lanes per edge (int4 = 8 halves each); 32 edges per iteration
__global__ void k_layer1(const float* __restrict__ W1,
                         const float* __restrict__ b1) {
    __shared__ float W1s[16 * 64];          // zero-padded to 16 rows
    __shared__ float b1s[64];
    __shared__ __align__(16) float sx[8][16];
    for (int i = threadIdx.x; i < 16 * 64; i += blockDim.x)
        W1s[i] = (i < 13 * 64) ? W1[i] : 0.0f;
    for (int i = threadIdx.x; i < 64; i += blockDim.x) b1s[i] = b1[i];
    __syncthreads();

    int warp = threadIdx.x >> 5;
    int v = (blockIdx.x * blockDim.x + threadIdx.x) >> 5;
    int lane = threadIdx.x & 31;
    if (v >= N_NODES) return;
    int sub = lane & 1, grp = lane >> 1;   // 16 edge groups

    float acc[8] = {0, 0, 0, 0, 0, 0, 0, 0};
    if (grp == 0) acc8(acc, g_x0h + v * 16 + sub * 8);   // self term h0'[v]

    int beg = g_rowptr[v], end = g_rowptr[v + 1];
    for (int t = beg; t < end; t += 32) {
        int i0 = t + grp, i1 = i0 + 16;
        if (i0 < end) acc8(acc, g_x0h + g_col[i0] * 16 + sub * 8);
        if (i1 < end) acc8(acc, g_x0h + g_col[i1] * 16 + sub * 8);
    }
#pragma unroll
    for (int off = 2; off <= 16; off <<= 1)
#pragma unroll
        for (int c = 0; c < 8; c++) acc[c] += __shfl_xor_sync(FULL, acc[c], off);

    if (lane < 2) {
        float4* s4 = (float4*)&sx[warp][sub * 8];
        s4[0] = make_float4(acc[0], acc[1], acc[2], acc[3]);
        s4[1] = make_float4(acc[4], acc[5], acc[6], acc[7]);
    }
    __syncwarp();

    float di = g_dinv[v];
    float ox = b1s[2 * lane], oy = b1s[2 * lane + 1];
    const float2* W1s2 = (const float2*)W1s;
#pragma unroll
    for (int k4 = 0; k4 < 4; k4++) {
        float4 a4 = ((const float4*)sx[warp])[k4];
        float av[4] = {a4.x * di, a4.y * di, a4.z * di, a4.w * di};
#pragma unroll
        for (int c = 0; c < 4; c++) {
            float2 w = W1s2[(4 * k4 + c) * 32 + lane];
            ox += av[c] * w.x;
            oy += av[c] * w.y;
        }
    }
    // relu, pre-scale by dinv for next layer, store fp16
    ((__half2*)(g_x1h + v * 64))[lane] =
        __floats2half2_rn(di * fmaxf(ox, 0.0f), di * fmaxf(oy, 0.0f));
}

// ---------------- layer 2: agg(x1')[64h] -> *dinv -> @W2 +b2 relu + x1 -> @W3 -> p' ----------------
// warp/node; 8 lanes per edge (int4 = 8 halves each); 8 edges per iteration
__global__ void k_layer2(const float* __restrict__ W2,
                         const float* __restrict__ b2,
                         const float* __restrict__ W3) {
    __shared__ float W2s[64 * 64];
    __shared__ float b2s[64];
    __shared__ float W3s[64 * 10];
    __shared__ __align__(16) float sagg[8][64];
    for (int i = threadIdx.x; i < 64 * 64; i += blockDim.x) W2s[i] = W2[i];
    for (int i = threadIdx.x; i < 64; i += blockDim.x) b2s[i] = b2[i];
    for (int i = threadIdx.x; i < 64 * 10; i += blockDim.x) W3s[i] = W3[i];
    __syncthreads();

    int warp = threadIdx.x >> 5;
    int v = (blockIdx.x * blockDim.x + threadIdx.x) >> 5;
    int lane = threadIdx.x & 31;
    if (v >= N_NODES) return;
    int sub = lane & 7, grp = lane >> 3;   // 4 edge groups

    float acc[8] = {0, 0, 0, 0, 0, 0, 0, 0};
    if (grp == 0) acc8(acc, g_x1h + v * 64 + sub * 8);   // self term h1'[v]

    int beg = g_rowptr[v], end = g_rowptr[v + 1];
    for (int t = beg; t < end; t += 8) {
        int i0 = t + grp, i1 = i0 + 4;
        if (i0 < end) acc8(acc, g_x1h + g_col[i0] * 64 + sub * 8);
        if (i1 < end) acc8(acc, g_x1h + g_col[i1] * 64 + sub * 8);
    }
#pragma unroll
    for (int off = 8; off <= 16; off <<= 1)
#pragma unroll
        for (int c = 0; c < 8; c++) acc[c] += __shfl_xor_sync(FULL, acc[c], off);

    if (lane < 8) {
        float4* s4 = (float4*)&sagg[warp][sub * 8];
        s4[0] = make_float4(acc[0], acc[1], acc[2], acc[3]);
        s4[1] = make_float4(acc[4], acc[5], acc[6], acc[7]);
    }
    __syncwarp();

    float di = g_dinv[v];
    float ox = b2s[2 * lane], oy = b2s[2 * lane + 1];
    const float2* W2s2 = (const float2*)W2s;
#pragma unroll
    for (int k4 = 0; k4 < 16; k4++) {
        float4 a4 = ((const float4*)sagg[warp])[k4];
        float av[4] = {a4.x * di, a4.y * di, a4.z * di, a4.w * di};
#pragma unroll
        for (int c = 0; c < 4; c++) {
            float2 w = W2s2[(4 * k4 + c) * 32 + lane];
            ox += av[c] * w.x;
            oy += av[c] * w.y;
        }
    }
    // relu + residual: x1[v] = h1'[v] / dinv[v]
    float rdeg = 1.0f / di;
    float2 r = __half22float2(((const __half2*)(g_x1h + v * 64))[lane]);
    float x2x = fmaxf(ox, 0.0f) + r.x * rdeg;
    float x2y = fmaxf(oy, 0.0f) + r.y * rdeg;

    // fused projection 64 -> 10
    float pj = 0.0f;
#pragma unroll
    for (int j = 0; j < 10; j++) {
        float pv = x2x * W3s[(2 * lane) * 10 + j] + x2y * W3s[(2 * lane + 1) * 10 + j];
        for (int off = 16; off; off >>= 1) pv += __shfl_xor_sync(FULL, pv, off);
        if (lane == j) pj = pv;
    }
    // pack p' = dinv*p into fp16 pairs; zero the 6 pad halves
    float phi = __shfl_sync(FULL, pj, (lane + 1) & 31);
    if (lane < 10 && (lane & 1) == 0)
        ((__half2*)(g_ph + v * 16))[lane >> 1] = __floats2half2_rn(di * pj, di * phi);
    else if (lane >= 10 && lane < 16 && (lane & 1) == 0)
        ((__half2*)(g_ph + v * 16))[lane >> 1] = __floats2half2_rn(0.0f, 0.0f);
}

// ---------------- layer 3: agg(p')[16h] -> *dinv + b3 -> log_softmax -> out ----------------
__global__ void k_layer3(const float* __restrict__ b3, float* __restrict__ out) {
    __shared__ __align__(16) float sp[8][16];
    int warp = threadIdx.x >> 5;
    int v = (blockIdx.x * blockDim.x + threadIdx.x) >> 5;
    int lane = threadIdx.x & 31;
    if (v >= N_NODES) return;
    int sub = lane & 1, grp = lane >> 1;

    float acc[8] = {0, 0, 0, 0, 0, 0, 0, 0};
    if (grp == 0) acc8(acc, g_ph + v * 16 + sub * 8);   // self term p'[v]

    int beg = g_rowptr[v], end = g_rowptr[v + 1];
    for (int t = beg; t < end; t += 32) {
        int i0 = t + grp, i1 = i0 + 16;
        if (i0 < end) acc8(acc, g_ph + g_col[i0] * 16 + sub * 8);
        if (i1 < end) acc8(acc, g_ph + g_col[i1] * 16 + sub * 8);
    }
#pragma unroll
    for (int off = 2; off <= 16; off <<= 1)
#pragma unroll
        for (int c = 0; c < 8; c++) acc[c] += __shfl_xor_sync(FULL, acc[c], off);

    if (lane < 2) {
        float4* s4 = (float4*)&sp[warp][sub * 8];
        s4[0] = make_float4(acc[0], acc[1], acc[2], acc[3]);
        s4[1] = make_float4(acc[4], acc[5], acc[6], acc[7]);
    }
    __syncwarp();

    float di = g_dinv[v];
    float z = (lane < 10) ? di * sp[warp][lane] + b3[lane] : -INFINITY;
    float mx = z;
    for (int off = 16; off; off >>= 1) mx = fmaxf(mx, __shfl_xor_sync(FULL, mx, off));
    float ex = (lane < 10) ? expf(z - mx) : 0.0f;
    float s = ex;
    for (int off = 16; off; off >>= 1) s += __shfl_xor_sync(FULL, s, off);
    if (lane < 10) out[v * 10 + lane] = z - mx - logf(s);
}

extern "C" void kernel_launch(void* const* d_in, const int* in_sizes, int n_in,
                              void* d_out, int out_size) {
    const float* x  = (const float*)d_in[0];
    const int*   ei = (const int*)d_in[1];
    const float* W1 = (const float*)d_in[2];
    const float* b1 = (const float*)d_in[3];
    const float* W2 = (const float*)d_in[4];
    const float* b2 = (const float*)d_in[5];
    const float* W3 = (const float*)d_in[6];
    const float* b3 = (const float*)d_in[7];
    float* out = (float*)d_out;

    const int TB = 256;
    int nodeBlocks  = (N_NODES + TB - 1) / TB;
    int hist4Blocks = (N_EDGES / 4 + TB - 1) / TB;
    int scat2Blocks = (N_EDGES / 2 + TB - 1) / TB;
    int warpNodeBlocks = (N_NODES * 32 + TB - 1) / TB;

    k_zero<<<nodeBlocks, TB>>>();
    k_hist<<<hist4Blocks, TB>>>(ei);
    k_blocksum<<<NB_SCAN, TB>>>();
    k_scanb<<<1, 512>>>();
    k_writerp<<<NB_SCAN, TB>>>();
    k_padx<<<nodeBlocks, TB>>>(x);
    k_scatter<<<scat2Blocks, TB>>>(ei);
    k_layer1<<<warpNodeBlocks, TB>>>(W1, b1);
    k_layer2<<<warpNodeBlocks, TB>>>(W2, b2, W3);
    k_layer3<<<warpNodeBlocks, TB>>>(b3, out);
}